// round 10
// baseline (speedup 1.0000x reference)
#include <cuda_runtime.h>

#define Bz 8
#define Hn 4
#define Ln 256
#define Dn 32

// One q-row per warp; 8 warps per CTA; no block-wide barriers anywhere.
__global__ __launch_bounds__(256)
void taa_kernel(const float* __restrict__ Q, const float* __restrict__ K,
                const float* __restrict__ V, const float* __restrict__ tmK,
                const float* __restrict__ tmV, const float* __restrict__ amask,
                const unsigned char* __restrict__ pad,
                float* __restrict__ x_out, float* __restrict__ attn_out)
{
    __shared__ float sE[8][Ln];          // warp-private 1 KB strips

    const int tid  = threadIdx.x;
    const int lane = tid & 31;
    const int wid  = tid >> 5;

    const int gq = blockIdx.x * 8 + wid;   // global (b,h,q) row: 0..8191
    const int q  = gq & (Ln - 1);
    const int bh = gq >> 8;
    const int b  = bh >> 2;                // Hn = 4

    const float* __restrict__ tmKq = tmK + (size_t)gq * Ln * Dn;
    const float* __restrict__ tmVq = tmV + (size_t)gq * Ln * Dn;
    const float* __restrict__ Kbh  = K + (size_t)bh * Ln * Dn;
    const float* __restrict__ Vbh  = V + (size_t)bh * Ln * Dn;

    const int kg = lane >> 3;    // 0..3 : which of 4 k-rows this lane handles
    const int dq = lane & 7;     // 0..7 : float4 chunk within D=32

    const float4 q4 = __ldg(reinterpret_cast<const float4*>(Q + (size_t)gq * Dn) + dq);
    float* __restrict__ sEw = sE[wid];

    // ---------- Phase 1: energy[k] = (tmK[k,:]+K[k,:]) . Q  (warp streams 32 KB) ----------
#pragma unroll 8
    for (int j = 0; j < 64; j++) {
        const int k = 4 * j + kg;
        const float4 tk = __ldcs(reinterpret_cast<const float4*>(tmKq + (size_t)k * Dn) + dq);
        const float4 kv = __ldg (reinterpret_cast<const float4*>(Kbh  + (size_t)k * Dn) + dq);
        float p = (tk.x + kv.x) * q4.x + (tk.y + kv.y) * q4.y
                + (tk.z + kv.z) * q4.z + (tk.w + kv.w) * q4.w;
        p += __shfl_down_sync(0xffffffffu, p, 4, 8);
        p += __shfl_down_sync(0xffffffffu, p, 2, 8);
        p += __shfl_down_sync(0xffffffffu, p, 1, 8);
        if (dq == 0) sEw[k] = p;
    }
    __syncwarp();

    // ---------- Softmax (fully warp-local, register-resident) ----------
    const float inv_scale = 0.17677669529663689f;   // 1/sqrt(32)
    float e[8];
    float m = -3.402823466e+38f;
#pragma unroll
    for (int i = 0; i < 8; i++) {
        const int k = lane + 32 * i;
        e[i] = sEw[k] * inv_scale + __ldg(&amask[q * Ln + k]);
        if (pad[b * Ln + k]) e[i] = -4294967295.0f;   // -2^32 + 1
        m = fmaxf(m, e[i]);
    }
#pragma unroll
    for (int o = 16; o > 0; o >>= 1) m = fmaxf(m, __shfl_xor_sync(0xffffffffu, m, o));

    float a[8];
    float s = 0.f;
#pragma unroll
    for (int i = 0; i < 8; i++) { a[i] = __expf(e[i] - m); s += a[i]; }
#pragma unroll
    for (int o = 16; o > 0; o >>= 1) s += __shfl_xor_sync(0xffffffffu, s, o);
    const float inv = __frcp_rn(s);

    float* __restrict__ arow = attn_out + (size_t)gq * Ln;
#pragma unroll
    for (int i = 0; i < 8; i++) {
        a[i] *= inv;
        sEw[lane + 32 * i] = a[i];
        __stcs(&arow[lane + 32 * i], a[i]);
    }
    __syncwarp();

    // ---------- Phase 2: x[d] = sum_k attn[k]*(tmV[k,d]+V[k,d])  (warp streams 32 KB) ----------
    float4 acc = make_float4(0.f, 0.f, 0.f, 0.f);
#pragma unroll 8
    for (int j = 0; j < 64; j++) {
        const int k = 4 * j + kg;
        const float av = sEw[k];                     // 8-lane broadcast, conflict-free
        const float4 tv = __ldcs(reinterpret_cast<const float4*>(tmVq + (size_t)k * Dn) + dq);
        const float4 vv = __ldg (reinterpret_cast<const float4*>(Vbh  + (size_t)k * Dn) + dq);
        acc.x += av * (tv.x + vv.x);
        acc.y += av * (tv.y + vv.y);
        acc.z += av * (tv.z + vv.z);
        acc.w += av * (tv.w + vv.w);
    }
    // Reduce across the 4 kg-groups (lanes differing in bits 3,4)
    acc.x += __shfl_xor_sync(0xffffffffu, acc.x, 8);
    acc.y += __shfl_xor_sync(0xffffffffu, acc.y, 8);
    acc.z += __shfl_xor_sync(0xffffffffu, acc.z, 8);
    acc.w += __shfl_xor_sync(0xffffffffu, acc.w, 8);
    acc.x += __shfl_xor_sync(0xffffffffu, acc.x, 16);
    acc.y += __shfl_xor_sync(0xffffffffu, acc.y, 16);
    acc.z += __shfl_xor_sync(0xffffffffu, acc.z, 16);
    acc.w += __shfl_xor_sync(0xffffffffu, acc.w, 16);

    if (lane < 8)
        __stcs(reinterpret_cast<float4*>(x_out + (size_t)gq * Dn) + lane, acc);
}

extern "C" void kernel_launch(void* const* d_in, const int* in_sizes, int n_in,
                              void* d_out, int out_size)
{
    const float* Q    = (const float*)d_in[0];
    const float* K    = (const float*)d_in[1];
    const float* V    = (const float*)d_in[2];
    const float* tmK  = (const float*)d_in[3];
    const float* tmV  = (const float*)d_in[4];
    const float* mask = (const float*)d_in[5];
    const unsigned char* pad = (const unsigned char*)d_in[6];

    float* out  = (float*)d_out;
    float* x    = out;                                // [B,H,L,D]
    float* attn = out + (size_t)Bz * Hn * Ln * Dn;    // [B,H,L,L]

    taa_kernel<<<Bz * Hn * Ln / 8, 256>>>(Q, K, V, tmK, tmV, mask, pad, x, attn);
}

// round 11
// speedup vs baseline: 1.1644x; 1.1644x over previous
#include <cuda_runtime.h>

#define Bz 8
#define Hn 4
#define Ln 256
#define Dn 32

__global__ __launch_bounds__(256, 4)
void taa_kernel(const float* __restrict__ Q, const float* __restrict__ K,
                const float* __restrict__ V, const float* __restrict__ tmK,
                const float* __restrict__ tmV, const float* __restrict__ amask,
                const unsigned char* __restrict__ pad,
                float* __restrict__ x_out, float* __restrict__ attn_out)
{
    __shared__ float sQ[Dn];
    __shared__ float sE[Ln];          // energy, then attn
    __shared__ float wmax[8];
    __shared__ float wsum[8];
    __shared__ float red[32 * Dn];    // 32 k0-groups x 32 d

    const int bid = blockIdx.x;
    const int q = bid & (Ln - 1);
    const int h = (bid >> 8) & (Hn - 1);
    const int b = bid >> 10;

    const int tid  = threadIdx.x;
    const int lane = tid & 31;
    const int wid  = tid >> 5;

    const int bh = b * Hn + h;
    const float* __restrict__ Qrow = Q   + ((size_t)bh * Ln + q) * Dn;
    const float* __restrict__ tmKq = tmK + (((size_t)bh * Ln + q) * Ln) * Dn;
    const float* __restrict__ tmVq = tmV + (((size_t)bh * Ln + q) * Ln) * Dn;
    const float* __restrict__ Kbh  = K + (size_t)bh * Ln * Dn;
    const float* __restrict__ Vbh  = V + (size_t)bh * Ln * Dn;

    if (tid < Dn) sQ[tid] = Qrow[tid];
    __syncthreads();

    const int k0 = tid >> 3;      // 0..31
    const int dq = tid & 7;       // 0..7 (float4 index within D=32)
    const float4 q4 = reinterpret_cast<const float4*>(sQ)[dq];

    // ---------------- Phase 1: energy[k] = (tmK[k,:]+K[k,:]) . Q ----------------
#pragma unroll
    for (int j = 0; j < 8; j++) {
        const int k = k0 + 32 * j;
        const float4 tk = __ldg(reinterpret_cast<const float4*>(tmKq + (size_t)k * Dn) + dq);
        const float4 kv = __ldg(reinterpret_cast<const float4*>(Kbh  + (size_t)k * Dn) + dq);
        float p = (tk.x + kv.x) * q4.x + (tk.y + kv.y) * q4.y
                + (tk.z + kv.z) * q4.z + (tk.w + kv.w) * q4.w;
        p += __shfl_down_sync(0xffffffffu, p, 4, 8);
        p += __shfl_down_sync(0xffffffffu, p, 2, 8);
        p += __shfl_down_sync(0xffffffffu, p, 1, 8);
        if (dq == 0) sE[k] = p;
    }
    __syncthreads();

    // ---------------- Softmax over k (row of 256) ----------------
    const float inv_scale = 0.17677669529663689f;   // 1/sqrt(32)
    float e = sE[tid] * inv_scale + amask[q * Ln + tid];
    if (pad[b * Ln + tid]) e = -4294967295.0f;      // -2^32 + 1

    float m = e;
#pragma unroll
    for (int o = 16; o > 0; o >>= 1) m = fmaxf(m, __shfl_xor_sync(0xffffffffu, m, o));
    if (lane == 0) wmax[wid] = m;
    __syncthreads();
    m = wmax[0];
#pragma unroll
    for (int i = 1; i < 8; i++) m = fmaxf(m, wmax[i]);

    const float ex = __expf(e - m);
    float s = ex;
#pragma unroll
    for (int o = 16; o > 0; o >>= 1) s += __shfl_xor_sync(0xffffffffu, s, o);
    if (lane == 0) wsum[wid] = s;
    __syncthreads();
    s = wsum[0];
#pragma unroll
    for (int i = 1; i < 8; i++) s += wsum[i];

    const float a = ex * __frcp_rn(s);
    __syncthreads();               // protect sE before overwrite (phase-1 reads done)
    sE[tid] = a;
    attn_out[((size_t)bh * Ln + q) * Ln + tid] = a;
    __syncthreads();

    // ---------------- Phase 2: x[d] = sum_k attn[k]*(tmV[k,d]+V[k,d]) ----------------
    float4 acc = make_float4(0.f, 0.f, 0.f, 0.f);
#pragma unroll
    for (int j = 0; j < 8; j++) {
        const int k = k0 + 32 * j;
        const float av = sE[k];
        const float4 tv = __ldg(reinterpret_cast<const float4*>(tmVq + (size_t)k * Dn) + dq);
        const float4 vv = __ldg(reinterpret_cast<const float4*>(Vbh  + (size_t)k * Dn) + dq);
        acc.x += av * (tv.x + vv.x);
        acc.y += av * (tv.y + vv.y);
        acc.z += av * (tv.z + vv.z);
        acc.w += av * (tv.w + vv.w);
    }
    reinterpret_cast<float4*>(red + k0 * Dn)[dq] = acc;
    __syncthreads();

    if (tid < Dn) {
        float xs = 0.f;
#pragma unroll
        for (int g = 0; g < 32; g++) xs += red[g * Dn + tid];
        x_out[((size_t)bh * Ln + q) * Dn + tid] = xs;
    }
}

extern "C" void kernel_launch(void* const* d_in, const int* in_sizes, int n_in,
                              void* d_out, int out_size)
{
    const float* Q    = (const float*)d_in[0];
    const float* K    = (const float*)d_in[1];
    const float* V    = (const float*)d_in[2];
    const float* tmK  = (const float*)d_in[3];
    const float* tmV  = (const float*)d_in[4];
    const float* mask = (const float*)d_in[5];
    const unsigned char* pad = (const unsigned char*)d_in[6];

    float* out  = (float*)d_out;
    float* x    = out;                                // [B,H,L,D]
    float* attn = out + (size_t)Bz * Hn * Ln * Dn;    // [B,H,L,L]

    taa_kernel<<<Bz * Hn * Ln, 256>>>(Q, K, V, tmK, tmV, mask, pad, x, attn);
}

// round 12
// speedup vs baseline: 1.1648x; 1.0004x over previous
#include <cuda_runtime.h>

#define Bz 8
#define Hn 4
#define Ln 256
#define Dn 32

__global__ __launch_bounds__(256, 4)
void taa_kernel(const float* __restrict__ Q, const float* __restrict__ K,
                const float* __restrict__ V, const float* __restrict__ tmK,
                const float* __restrict__ tmV, const float* __restrict__ amask,
                const unsigned char* __restrict__ pad,
                float* __restrict__ x_out, float* __restrict__ attn_out)
{
    __shared__ float sQ[Dn];
    __shared__ float sE[Ln];          // energy, then attn
    __shared__ float wmax[8];
    __shared__ float wsum[8];
    __shared__ float red[32 * Dn];    // 32 k0-groups x 32 d

    const int bid = blockIdx.x;
    const int q = bid & (Ln - 1);
    const int h = (bid >> 8) & (Hn - 1);
    const int b = bid >> 10;

    const int tid  = threadIdx.x;
    const int lane = tid & 31;
    const int wid  = tid >> 5;

    const int bh = b * Hn + h;
    const float* __restrict__ Qrow = Q   + ((size_t)bh * Ln + q) * Dn;
    const float* __restrict__ tmKq = tmK + (((size_t)bh * Ln + q) * Ln) * Dn;
    const float* __restrict__ tmVq = tmV + (((size_t)bh * Ln + q) * Ln) * Dn;
    const float* __restrict__ Kbh  = K + (size_t)bh * Ln * Dn;
    const float* __restrict__ Vbh  = V + (size_t)bh * Ln * Dn;

    if (tid < Dn) sQ[tid] = Qrow[tid];
    __syncthreads();

    const int k0 = tid >> 3;      // 0..31
    const int dq = tid & 7;       // 0..7 (float4 index within D=32)
    const float4 q4 = reinterpret_cast<const float4*>(sQ)[dq];

    // ---------------- Phase 1: energy[k] = (tmK[k,:]+K[k,:]) . Q ----------------
#pragma unroll
    for (int j = 0; j < 8; j++) {
        const int k = k0 + 32 * j;
        const float4 tk = __ldg(reinterpret_cast<const float4*>(tmKq + (size_t)k * Dn) + dq);
        const float4 kv = __ldg(reinterpret_cast<const float4*>(Kbh  + (size_t)k * Dn) + dq);
        float p = (tk.x + kv.x) * q4.x + (tk.y + kv.y) * q4.y
                + (tk.z + kv.z) * q4.z + (tk.w + kv.w) * q4.w;
        p += __shfl_down_sync(0xffffffffu, p, 4, 8);
        p += __shfl_down_sync(0xffffffffu, p, 2, 8);
        p += __shfl_down_sync(0xffffffffu, p, 1, 8);
        if (dq == 0) sE[k] = p;
    }
    __syncthreads();

    // ---------------- Softmax over k (row of 256) ----------------
    const float inv_scale = 0.17677669529663689f;   // 1/sqrt(32)
    float e = sE[tid] * inv_scale + amask[q * Ln + tid];
    if (pad[b * Ln + tid]) e = -4294967295.0f;      // -2^32 + 1

    float m = e;
#pragma unroll
    for (int o = 16; o > 0; o >>= 1) m = fmaxf(m, __shfl_xor_sync(0xffffffffu, m, o));
    if (lane == 0) wmax[wid] = m;
    __syncthreads();
    m = wmax[0];
#pragma unroll
    for (int i = 1; i < 8; i++) m = fmaxf(m, wmax[i]);

    const float ex = __expf(e - m);
    float s = ex;
#pragma unroll
    for (int o = 16; o > 0; o >>= 1) s += __shfl_xor_sync(0xffffffffu, s, o);
    if (lane == 0) wsum[wid] = s;
    __syncthreads();
    s = wsum[0];
#pragma unroll
    for (int i = 1; i < 8; i++) s += wsum[i];

    // sE[tid] was read only by this thread (before the wmax barrier), so the
    // overwrite needs no preceding barrier; the one after publishes attn.
    const float a = ex * __frcp_rn(s);
    sE[tid] = a;
    attn_out[((size_t)bh * Ln + q) * Ln + tid] = a;
    __syncthreads();

    // ---------------- Phase 2: x[d] = sum_k attn[k]*(tmV[k,d]+V[k,d]) ----------------
    float4 acc = make_float4(0.f, 0.f, 0.f, 0.f);
#pragma unroll
    for (int j = 0; j < 8; j++) {
        const int k = k0 + 32 * j;
        const float av = sE[k];
        const float4 tv = __ldg(reinterpret_cast<const float4*>(tmVq + (size_t)k * Dn) + dq);
        const float4 vv = __ldg(reinterpret_cast<const float4*>(Vbh  + (size_t)k * Dn) + dq);
        acc.x += av * (tv.x + vv.x);
        acc.y += av * (tv.y + vv.y);
        acc.z += av * (tv.z + vv.z);
        acc.w += av * (tv.w + vv.w);
    }
    reinterpret_cast<float4*>(red + k0 * Dn)[dq] = acc;
    __syncthreads();

    if (tid < Dn) {
        float xs = 0.f;
#pragma unroll
        for (int g = 0; g < 32; g++) xs += red[g * Dn + tid];
        x_out[((size_t)bh * Ln + q) * Dn + tid] = xs;
    }
}

extern "C" void kernel_launch(void* const* d_in, const int* in_sizes, int n_in,
                              void* d_out, int out_size)
{
    const float* Q    = (const float*)d_in[0];
    const float* K    = (const float*)d_in[1];
    const float* V    = (const float*)d_in[2];
    const float* tmK  = (const float*)d_in[3];
    const float* tmV  = (const float*)d_in[4];
    const float* mask = (const float*)d_in[5];
    const unsigned char* pad = (const unsigned char*)d_in[6];

    float* out  = (float*)d_out;
    float* x    = out;                                // [B,H,L,D]
    float* attn = out + (size_t)Bz * Hn * Ln * Dn;    // [B,H,L,L]

    taa_kernel<<<Bz * Hn * Ln, 256>>>(Q, K, V, tmK, tmV, mask, pad, x, attn);
}

// round 13
// speedup vs baseline: 1.1733x; 1.0073x over previous
#include <cuda_runtime.h>

#define Bz 8
#define Hn 4
#define Ln 256
#define Dn 32

__global__ __launch_bounds__(256, 4)
void taa_kernel(const float* __restrict__ Q, const float* __restrict__ K,
                const float* __restrict__ V, const float* __restrict__ tmK,
                const float* __restrict__ tmV, const float* __restrict__ amask,
                const unsigned char* __restrict__ pad,
                float* __restrict__ x_out, float* __restrict__ attn_out)
{
    __shared__ float sQ[Dn];
    __shared__ float sE[Ln];          // energy, then attn
    __shared__ float2 wms[8];         // per-warp (max, sum) pairs
    __shared__ float red[32 * Dn];    // 32 k0-groups x 32 d

    const int bid = blockIdx.x;
    const int q = bid & (Ln - 1);
    const int h = (bid >> 8) & (Hn - 1);
    const int b = bid >> 10;

    const int tid  = threadIdx.x;
    const int lane = tid & 31;
    const int wid  = tid >> 5;

    const int bh = b * Hn + h;
    const float* __restrict__ Qrow = Q   + ((size_t)bh * Ln + q) * Dn;
    const float* __restrict__ tmKq = tmK + (((size_t)bh * Ln + q) * Ln) * Dn;
    const float* __restrict__ tmVq = tmV + (((size_t)bh * Ln + q) * Ln) * Dn;
    const float* __restrict__ Kbh  = K + (size_t)bh * Ln * Dn;
    const float* __restrict__ Vbh  = V + (size_t)bh * Ln * Dn;

    // Fold 1/sqrt(D) into Q once: energy/scale == (scaled Q) dot (tmK+K).
    if (tid < Dn) sQ[tid] = Qrow[tid] * 0.17677669529663689f;
    __syncthreads();

    const int k0 = tid >> 3;      // 0..31
    const int dq = tid & 7;       // 0..7 (float4 index within D=32)
    const float4 q4 = reinterpret_cast<const float4*>(sQ)[dq];

    // ---------------- Phase 1: energy[k] = (tmK[k,:]+K[k,:]) . Qs ----------------
#pragma unroll
    for (int j = 0; j < 8; j++) {
        const int k = k0 + 32 * j;
        const float4 tk = __ldg(reinterpret_cast<const float4*>(tmKq + (size_t)k * Dn) + dq);
        const float4 kv = __ldg(reinterpret_cast<const float4*>(Kbh  + (size_t)k * Dn) + dq);
        float p = (tk.x + kv.x) * q4.x + (tk.y + kv.y) * q4.y
                + (tk.z + kv.z) * q4.z + (tk.w + kv.w) * q4.w;
        p += __shfl_down_sync(0xffffffffu, p, 4, 8);
        p += __shfl_down_sync(0xffffffffu, p, 2, 8);
        p += __shfl_down_sync(0xffffffffu, p, 1, 8);
        if (dq == 0) sE[k] = p;
    }
    __syncthreads();

    // ---------------- Softmax: single-barrier online combine ----------------
    float e = sE[tid] + amask[q * Ln + tid];
    if (pad[b * Ln + tid]) e = -4294967295.0f;      // -2^32 + 1

    // Per-warp max then per-warp sum of exp(e - m_w): shuffles only.
    float mw = e;
#pragma unroll
    for (int o = 16; o > 0; o >>= 1) mw = fmaxf(mw, __shfl_xor_sync(0xffffffffu, mw, o));
    const float exl = __expf(e - mw);
    float sw = exl;
#pragma unroll
    for (int o = 16; o > 0; o >>= 1) sw += __shfl_xor_sync(0xffffffffu, sw, o);
    if (lane == 0) wms[wid] = make_float2(mw, sw);
    __syncthreads();

    // Combine the 8 (m_w, s_w) pairs: M = max, S = sum s_w * exp(m_w - M).
    float M = wms[0].x;
#pragma unroll
    for (int i = 1; i < 8; i++) M = fmaxf(M, wms[i].x);
    float S = 0.f;
#pragma unroll
    for (int i = 0; i < 8; i++) S += wms[i].y * __expf(wms[i].x - M);

    const float a = exl * __expf(mw - M) * __frcp_rn(S);
    // sE[tid] was read only by this thread (pre-barrier), safe to overwrite.
    sE[tid] = a;
    attn_out[((size_t)bh * Ln + q) * Ln + tid] = a;
    __syncthreads();

    // ---------------- Phase 2: x[d] = sum_k attn[k]*(tmV[k,d]+V[k,d]) ----------------
    float4 acc = make_float4(0.f, 0.f, 0.f, 0.f);
#pragma unroll
    for (int j = 0; j < 8; j++) {
        const int k = k0 + 32 * j;
        const float av = sE[k];
        const float4 tv = __ldg(reinterpret_cast<const float4*>(tmVq + (size_t)k * Dn) + dq);
        const float4 vv = __ldg(reinterpret_cast<const float4*>(Vbh  + (size_t)k * Dn) + dq);
        acc.x += av * (tv.x + vv.x);
        acc.y += av * (tv.y + vv.y);
        acc.z += av * (tv.z + vv.z);
        acc.w += av * (tv.w + vv.w);
    }
    reinterpret_cast<float4*>(red + k0 * Dn)[dq] = acc;
    __syncthreads();

    if (tid < Dn) {
        float xs = 0.f;
#pragma unroll
        for (int g = 0; g < 32; g++) xs += red[g * Dn + tid];
        x_out[((size_t)bh * Ln + q) * Dn + tid] = xs;
    }
}

extern "C" void kernel_launch(void* const* d_in, const int* in_sizes, int n_in,
                              void* d_out, int out_size)
{
    const float* Q    = (const float*)d_in[0];
    const float* K    = (const float*)d_in[1];
    const float* V    = (const float*)d_in[2];
    const float* tmK  = (const float*)d_in[3];
    const float* tmV  = (const float*)d_in[4];
    const float* mask = (const float*)d_in[5];
    const unsigned char* pad = (const unsigned char*)d_in[6];

    float* out  = (float*)d_out;
    float* x    = out;                                // [B,H,L,D]
    float* attn = out + (size_t)Bz * Hn * Ln * Dn;    // [B,H,L,L]

    taa_kernel<<<Bz * Hn * Ln, 256>>>(Q, K, V, tmK, tmV, mask, pad, x, attn);
}

// round 14
// speedup vs baseline: 1.1829x; 1.0081x over previous
#include <cuda_runtime.h>

#define Bz 8
#define Hn 4
#define Ln 256
#define Dn 32

__global__ __launch_bounds__(256, 4)
void taa_kernel(const float* __restrict__ Q, const float* __restrict__ K,
                const float* __restrict__ V, const float* __restrict__ tmK,
                const float* __restrict__ tmV, const float* __restrict__ amask,
                const unsigned char* __restrict__ pad,
                float* __restrict__ x_out, float* __restrict__ attn_out)
{
    __shared__ float sQ[Dn];
    __shared__ float sE[Ln];          // energy, then attn
    __shared__ float2 wms[8];         // per-warp (max, sum) pairs
    __shared__ float red[32 * Dn];    // 32 k0-groups x 32 d
    __shared__ float red2[8 * Dn];    // second-stage partials

    const int bid = blockIdx.x;
    const int q = bid & (Ln - 1);
    const int h = (bid >> 8) & (Hn - 1);
    const int b = bid >> 10;

    const int tid  = threadIdx.x;
    const int lane = tid & 31;
    const int wid  = tid >> 5;

    const int bh = b * Hn + h;
    const float* __restrict__ Qrow = Q   + ((size_t)bh * Ln + q) * Dn;
    const float* __restrict__ tmKq = tmK + (((size_t)bh * Ln + q) * Ln) * Dn;
    const float* __restrict__ tmVq = tmV + (((size_t)bh * Ln + q) * Ln) * Dn;
    const float* __restrict__ Kbh  = K + (size_t)bh * Ln * Dn;
    const float* __restrict__ Vbh  = V + (size_t)bh * Ln * Dn;

    // Fold 1/sqrt(D) into Q once.
    if (tid < Dn) sQ[tid] = Qrow[tid] * 0.17677669529663689f;
    __syncthreads();

    const int k0 = tid >> 3;      // 0..31
    const int dq = tid & 7;       // 0..7 (float4 index within D=32)
    const float4 q4 = reinterpret_cast<const float4*>(sQ)[dq];

    // ---------------- Phase 1: energy[k] = (tmK[k,:]+K[k,:]) . Qs ----------------
#pragma unroll
    for (int j = 0; j < 8; j++) {
        const int k = k0 + 32 * j;
        const float4 tk = __ldg(reinterpret_cast<const float4*>(tmKq + (size_t)k * Dn) + dq);
        const float4 kv = __ldg(reinterpret_cast<const float4*>(Kbh  + (size_t)k * Dn) + dq);
        float p = (tk.x + kv.x) * q4.x + (tk.y + kv.y) * q4.y
                + (tk.z + kv.z) * q4.z + (tk.w + kv.w) * q4.w;
        p += __shfl_down_sync(0xffffffffu, p, 4, 8);
        p += __shfl_down_sync(0xffffffffu, p, 2, 8);
        p += __shfl_down_sync(0xffffffffu, p, 1, 8);
        if (dq == 0) sE[k] = p;
    }
    __syncthreads();

    // ---------------- Softmax: single-barrier online combine ----------------
    float e = sE[tid] + amask[q * Ln + tid];
    if (pad[b * Ln + tid]) e = -4294967295.0f;      // -2^32 + 1

    float mw = e;
#pragma unroll
    for (int o = 16; o > 0; o >>= 1) mw = fmaxf(mw, __shfl_xor_sync(0xffffffffu, mw, o));
    const float exl = __expf(e - mw);
    float sw = exl;
#pragma unroll
    for (int o = 16; o > 0; o >>= 1) sw += __shfl_xor_sync(0xffffffffu, sw, o);
    if (lane == 0) wms[wid] = make_float2(mw, sw);
    __syncthreads();

    float M = wms[0].x;
#pragma unroll
    for (int i = 1; i < 8; i++) M = fmaxf(M, wms[i].x);
    float S = 0.f;
#pragma unroll
    for (int i = 0; i < 8; i++) S += wms[i].y * __expf(wms[i].x - M);

    const float a = exl * __expf(mw - M) * __frcp_rn(S);
    sE[tid] = a;                  // sole prior reader was this thread
    attn_out[((size_t)bh * Ln + q) * Ln + tid] = a;
    __syncthreads();

    // ---------------- Phase 2: x[d] = sum_k attn[k]*(tmV[k,d]+V[k,d]) ----------------
    float4 acc = make_float4(0.f, 0.f, 0.f, 0.f);
#pragma unroll
    for (int j = 0; j < 8; j++) {
        const int k = k0 + 32 * j;
        const float av = sE[k];
        const float4 tv = __ldg(reinterpret_cast<const float4*>(tmVq + (size_t)k * Dn) + dq);
        const float4 vv = __ldg(reinterpret_cast<const float4*>(Vbh  + (size_t)k * Dn) + dq);
        acc.x += av * (tv.x + vv.x);
        acc.y += av * (tv.y + vv.y);
        acc.z += av * (tv.z + vv.z);
        acc.w += av * (tv.w + vv.w);
    }
    reinterpret_cast<float4*>(red + k0 * Dn)[dq] = acc;
    __syncthreads();

    // Two-stage tail reduction using all 256 threads:
    // stage 1: thread (g0, d) sums groups {g0, g0+8, g0+16, g0+24} for dim d.
    {
        const int d  = tid & 31;
        const int g0 = tid >> 5;     // 0..7
        float ps = red[g0 * Dn + d] + red[(g0 + 8) * Dn + d]
                 + red[(g0 + 16) * Dn + d] + red[(g0 + 24) * Dn + d];
        red2[g0 * Dn + d] = ps;
    }
    __syncthreads();

    // stage 2: 32 threads sum the 8 partials per dim and store x.
    if (tid < Dn) {
        float xs = 0.f;
#pragma unroll
        for (int g = 0; g < 8; g++) xs += red2[g * Dn + tid];
        x_out[((size_t)bh * Ln + q) * Dn + tid] = xs;
    }
}

extern "C" void kernel_launch(void* const* d_in, const int* in_sizes, int n_in,
                              void* d_out, int out_size)
{
    const float* Q    = (const float*)d_in[0];
    const float* K    = (const float*)d_in[1];
    const float* V    = (const float*)d_in[2];
    const float* tmK  = (const float*)d_in[3];
    const float* tmV  = (const float*)d_in[4];
    const float* mask = (const float*)d_in[5];
    const unsigned char* pad = (const unsigned char*)d_in[6];

    float* out  = (float*)d_out;
    float* x    = out;                                // [B,H,L,D]
    float* attn = out + (size_t)Bz * Hn * Ln * Dn;    // [B,H,L,L]

    taa_kernel<<<Bz * Hn * Ln, 256>>>(Q, K, V, tmK, tmV, mask, pad, x, attn);
}

// round 15
// speedup vs baseline: 1.1846x; 1.0015x over previous
#include <cuda_runtime.h>

#define Bz 8
#define Hn 4
#define Ln 256
#define Dn 32

__global__ __launch_bounds__(256, 4)
void taa_kernel(const float* __restrict__ Q, const float* __restrict__ K,
                const float* __restrict__ V, const float* __restrict__ tmK,
                const float* __restrict__ tmV, const float* __restrict__ amask,
                const unsigned char* __restrict__ pad,
                float* __restrict__ x_out, float* __restrict__ attn_out)
{
    __shared__ float sQ[Dn];
    __shared__ float sE[Ln];          // energy, then attn
    __shared__ float2 wms[8];         // per-warp (max, sum) pairs
    __shared__ float red[32 * Dn];    // 32 k0-groups x 32 d
    __shared__ float red2[8 * Dn];    // second-stage partials

    const int bid = blockIdx.x;
    const int q = bid & (Ln - 1);
    const int h = (bid >> 8) & (Hn - 1);
    const int b = bid >> 10;

    const int tid  = threadIdx.x;
    const int lane = tid & 31;
    const int wid  = tid >> 5;

    const int bh = b * Hn + h;
    const float* __restrict__ Qrow = Q   + ((size_t)bh * Ln + q) * Dn;
    const float* __restrict__ tmKq = tmK + (((size_t)bh * Ln + q) * Ln) * Dn;
    const float* __restrict__ tmVq = tmV + (((size_t)bh * Ln + q) * Ln) * Dn;
    const float* __restrict__ Kbh  = K + (size_t)bh * Ln * Dn;
    const float* __restrict__ Vbh  = V + (size_t)bh * Ln * Dn;

    // Fold 1/sqrt(D) into Q once.
    if (tid < Dn) sQ[tid] = Qrow[tid] * 0.17677669529663689f;
    __syncthreads();

    const int k0 = tid >> 3;      // 0..31
    const int dq = tid & 7;       // 0..7 (float4 index within D=32)
    const float4 q4 = reinterpret_cast<const float4*>(sQ)[dq];

    // ---------------- Phase 1: energy[k] = (tmK[k,:]+K[k,:]) . Qs ----------------
#pragma unroll
    for (int j = 0; j < 8; j++) {
        const int k = k0 + 32 * j;
        const float4 tk = __ldg(reinterpret_cast<const float4*>(tmKq + (size_t)k * Dn) + dq);
        const float4 kv = __ldg(reinterpret_cast<const float4*>(Kbh  + (size_t)k * Dn) + dq);
        float p = (tk.x + kv.x) * q4.x + (tk.y + kv.y) * q4.y
                + (tk.z + kv.z) * q4.z + (tk.w + kv.w) * q4.w;
        p += __shfl_down_sync(0xffffffffu, p, 4, 8);
        p += __shfl_down_sync(0xffffffffu, p, 2, 8);
        p += __shfl_down_sync(0xffffffffu, p, 1, 8);
        if (dq == 0) sE[k] = p;
    }
    __syncthreads();

    // ---------------- Softmax: single-barrier online combine ----------------
    float e = sE[tid] + amask[q * Ln + tid];
    if (pad[b * Ln + tid]) e = -4294967295.0f;      // -2^32 + 1

    float mw = e;
#pragma unroll
    for (int o = 16; o > 0; o >>= 1) mw = fmaxf(mw, __shfl_xor_sync(0xffffffffu, mw, o));
    const float exl = __expf(e - mw);
    float sw = exl;
#pragma unroll
    for (int o = 16; o > 0; o >>= 1) sw += __shfl_xor_sync(0xffffffffu, sw, o);
    if (lane == 0) wms[wid] = make_float2(mw, sw);
    __syncthreads();

    float M = wms[0].x;
#pragma unroll
    for (int i = 1; i < 8; i++) M = fmaxf(M, wms[i].x);
    float S = 0.f;
#pragma unroll
    for (int i = 0; i < 8; i++) S += wms[i].y * __expf(wms[i].x - M);

    const float a = exl * __expf(mw - M) * __frcp_rn(S);
    sE[tid] = a;                  // sole prior reader was this thread
    attn_out[((size_t)bh * Ln + q) * Ln + tid] = a;
    __syncthreads();

    // ---------------- Phase 2: x[d] = sum_k attn[k]*(tmV[k,d]+V[k,d]) ----------------
    float4 acc = make_float4(0.f, 0.f, 0.f, 0.f);
#pragma unroll
    for (int j = 0; j < 8; j++) {
        const int k = k0 + 32 * j;
        const float av = sE[k];
        const float4 tv = __ldg(reinterpret_cast<const float4*>(tmVq + (size_t)k * Dn) + dq);
        const float4 vv = __ldg(reinterpret_cast<const float4*>(Vbh  + (size_t)k * Dn) + dq);
        acc.x += av * (tv.x + vv.x);
        acc.y += av * (tv.y + vv.y);
        acc.z += av * (tv.z + vv.z);
        acc.w += av * (tv.w + vv.w);
    }
    reinterpret_cast<float4*>(red + k0 * Dn)[dq] = acc;
    __syncthreads();

    // Two-stage tail reduction using all 256 threads.
    {
        const int d  = tid & 31;
        const int g0 = tid >> 5;     // 0..7
        float ps = red[g0 * Dn + d] + red[(g0 + 8) * Dn + d]
                 + red[(g0 + 16) * Dn + d] + red[(g0 + 24) * Dn + d];
        red2[g0 * Dn + d] = ps;
    }
    __syncthreads();

    if (tid < Dn) {
        float xs = 0.f;
#pragma unroll
        for (int g = 0; g < 8; g++) xs += red2[g * Dn + tid];
        x_out[((size_t)bh * Ln + q) * Dn + tid] = xs;
    }
}

extern "C" void kernel_launch(void* const* d_in, const int* in_sizes, int n_in,
                              void* d_out, int out_size)
{
    const float* Q    = (const float*)d_in[0];
    const float* K    = (const float*)d_in[1];
    const float* V    = (const float*)d_in[2];
    const float* tmK  = (const float*)d_in[3];
    const float* tmV  = (const float*)d_in[4];
    const float* mask = (const float*)d_in[5];
    const unsigned char* pad = (const unsigned char*)d_in[6];

    float* out  = (float*)d_out;
    float* x    = out;                                // [B,H,L,D]
    float* attn = out + (size_t)Bz * Hn * Ln * Dn;    // [B,H,L,L]

    taa_kernel<<<Bz * Hn * Ln, 256>>>(Q, K, V, tmK, tmV, mask, pad, x, attn);
}